// round 9
// baseline (speedup 1.0000x reference)
#include <cuda_runtime.h>
#include <cuda_fp16.h>
#include <cstdint>
#include <cstddef>

#define S_ 4
#define B_ 512
#define D_ 256
#define H_ 1024
#define T_ 50
#define M_ (S_*B_)          // 2048
#define PRED (M_*T_*D_)
#define GRID_CTAS 128

// ---------------- device scratch (no allocation allowed) ----------------
__device__ __half g_A [M_*D_];       // layer-1 input (probe state), fp16
__device__ __half g_H1[M_*H_];
__device__ __half g_H2[M_*H_];
__device__ float g_K1[M_*D_], g_K2[M_*D_], g_K3[M_*D_], g_Y[M_*D_];
__device__ __half g_W1[H_*D_];       // weights transposed [N,K] fp16
__device__ __half g_W2[H_*H_];
__device__ __half g_W3[D_*H_];
__device__ unsigned g_bar_cnt;
__device__ unsigned g_bar_gen;

// ---------------- helpers ----------------
__device__ __forceinline__ uint32_t smem_u32(const void* p) {
    uint32_t a;
    asm("{ .reg .u64 t; cvta.to.shared.u64 t, %1; cvt.u32.u64 %0, t; }" : "=r"(a) : "l"(p));
    return a;
}
__device__ __forceinline__ void cp_async16(uint32_t saddr, const void* gaddr) {
    asm volatile("cp.async.cg.shared.global [%0], [%1], 16;" :: "r"(saddr), "l"(gaddr));
}
#define CP_COMMIT() asm volatile("cp.async.commit_group;" ::: "memory")
#define CP_WAIT1()  asm volatile("cp.async.wait_group 1;" ::: "memory")

__device__ __forceinline__ void ldsm_x4(uint32_t* r, uint32_t addr) {
    asm volatile("ldmatrix.sync.aligned.m8n8.x4.shared.b16 {%0,%1,%2,%3}, [%4];"
                 : "=r"(r[0]), "=r"(r[1]), "=r"(r[2]), "=r"(r[3]) : "r"(addr));
}
__device__ __forceinline__ void mma16816(float* c, const uint32_t* a, uint32_t b0, uint32_t b1) {
    asm volatile("mma.sync.aligned.m16n8k16.row.col.f32.f16.f16.f32 "
                 "{%0,%1,%2,%3}, {%4,%5,%6,%7}, {%8,%9}, {%0,%1,%2,%3};"
                 : "+f"(c[0]), "+f"(c[1]), "+f"(c[2]), "+f"(c[3])
                 : "r"(a[0]), "r"(a[1]), "r"(a[2]), "r"(a[3]), "r"(b0), "r"(b1));
}

__device__ __forceinline__ float fast_tanh(float x) {
    float t = __expf(2.0f * x);
    return 1.0f - 2.0f / (t + 1.0f);
}
__device__ __forceinline__ uint32_t pack_h2(float a, float b) {
    __half2 h = __floats2half2_rn(a, b);
    return *reinterpret_cast<uint32_t*>(&h);
}

// grid-wide barrier: count with acq_rel RMW, generation bumped with release,
// spinners acquire-load the generation. Counters reset each replay by init_k.
__device__ __forceinline__ void grid_barrier(unsigned target) {
    __syncthreads();
    if (threadIdx.x == 0) {
        __threadfence();
        unsigned old;
        asm volatile("atom.acq_rel.gpu.global.add.u32 %0, [%1], 1;"
                     : "=r"(old) : "l"(&g_bar_cnt) : "memory");
        if (old + 1u == target * (unsigned)GRID_CTAS) {
            asm volatile("red.release.gpu.global.add.u32 [%0], 1;"
                         :: "l"(&g_bar_gen) : "memory");
        } else {
            unsigned g;
            do {
                asm volatile("ld.acquire.gpu.global.u32 %0, [%1];"
                             : "=r"(g) : "l"(&g_bar_gen) : "memory");
            } while (g < target);
        }
    }
    __syncthreads();
}

// ---------------- one GEMM phase (device function) ----------------
// C[M, NFULL] = A[M,KDIM] @ W^T + bias, fused RK4 epilogues as before.
template<int BM, int BN, int WM, int WN, int KDIM, int NFULL, int EPI>
__device__ __forceinline__ void gemm_phase(
        char* sm, uint32_t smb,
        const __half* __restrict__ A, const __half* __restrict__ W,
        const float* __restrict__ bias, __half* __restrict__ O,
        float* __restrict__ Kout,
        const float* __restrict__ K1c, const float* __restrict__ K2c, const float* __restrict__ K3c,
        float* __restrict__ Ybuf, float* __restrict__ dout,
        float dt, int step, float alpha)
{
    constexpr int WARPS_M = BM / WM;
    constexpr int NC      = KDIM / 64;
    constexpr int STAGE   = (BM + BN) * 128;
    constexpr int MI = WM / 16, NJ = WN / 8, NJJ = WN / 16;

    const int tid  = threadIdx.x;
    const int wid  = tid >> 5, lane = tid & 31;
    const int wm   = wid % WARPS_M, wn = wid / WARPS_M;
    const int bid  = blockIdx.x;
    const int bn   = (bid % (NFULL / BN)) * BN;
    const int bm   = (bid / (NFULL / BN)) * BM;

    float acc[MI][NJ][4];
    #pragma unroll
    for (int i = 0; i < MI; i++)
        #pragma unroll
        for (int j = 0; j < NJ; j++)
            #pragma unroll
            for (int q = 0; q < 4; q++) acc[i][j][q] = 0.0f;

    auto load_chunk = [&](int c, int slot) {
        const int k0 = c * 64;
        const uint32_t sb = smb + (uint32_t)slot * STAGE;
        #pragma unroll
        for (int i = tid; i < (BM + BN) * 8; i += 256) {
            const int seg = i & 7;
            const bool isA = i < BM * 8;
            const int row  = (isA ? i : i - BM * 8) >> 3;
            const __half* src = isA
                ? A + (size_t)(bm + row) * KDIM + k0 + seg * 8
                : W + (size_t)(bn + row) * KDIM + k0 + seg * 8;
            const uint32_t base = sb + (uint32_t)((isA ? row : BM + row)) * 128;
            cp_async16(base + (uint32_t)((seg ^ (row & 7)) << 4), src);
        }
    };

    load_chunk(0, 0); CP_COMMIT();
    load_chunk(1, 1); CP_COMMIT();

    const int oct = lane >> 3, lr = lane & 7;

    for (int c = 0; c < NC; c++) {
        CP_WAIT1();
        __syncthreads();
        if (c + 2 < NC) load_chunk(c + 2, (c + 2) % 3);
        CP_COMMIT();

        const uint32_t sb = smb + (uint32_t)(c % 3) * STAGE;
        const uint32_t Ab = sb;
        const uint32_t Bb = sb + BM * 128;

        #pragma unroll
        for (int t = 0; t < 4; t++) {
            uint32_t af[MI][4], bf[NJJ][4];
            #pragma unroll
            for (int i = 0; i < MI; i++) {
                const int row = wm * WM + i * 16 + (oct & 1) * 8 + lr;
                const int ks  = t * 2 + (oct >> 1);
                ldsm_x4(af[i], Ab + (uint32_t)row * 128 + (uint32_t)((ks ^ (row & 7)) << 4));
            }
            #pragma unroll
            for (int jj = 0; jj < NJJ; jj++) {
                const int row = wn * WN + jj * 16 + (oct >> 1) * 8 + lr;
                const int ks  = t * 2 + (oct & 1);
                ldsm_x4(bf[jj], Bb + (uint32_t)row * 128 + (uint32_t)((ks ^ (row & 7)) << 4));
            }
            #pragma unroll
            for (int i = 0; i < MI; i++)
                #pragma unroll
                for (int j = 0; j < NJ; j++)
                    mma16816(acc[i][j], af[i], bf[j >> 1][(j & 1) * 2], bf[j >> 1][(j & 1) * 2 + 1]);
        }
    }
    __syncthreads();   // all warps done with smem before next phase reuses it

    const float ad = alpha * dt;
    const float c6 = dt * (1.0f / 6.0f);
    const int r00   = bm + wm * WM + (lane >> 2);
    const int cbase = bn + wn * WN + (lane & 3) * 2;

    #pragma unroll
    for (int i = 0; i < MI; i++) {
        #pragma unroll
        for (int j = 0; j < NJ; j++) {
            const int cc = cbase + j * 8;
            const float2 bs = *(const float2*)&bias[cc];
            const int rows[2] = { r00 + i * 16, r00 + i * 16 + 8 };
            #pragma unroll
            for (int h = 0; h < 2; h++) {
                float v0 = acc[i][j][2*h + 0] + bs.x;
                float v1 = acc[i][j][2*h + 1] + bs.y;
                const size_t idx = (size_t)rows[h] * NFULL + cc;
                if (EPI == 0) {
                    v0 = fast_tanh(v0); v1 = fast_tanh(v1);
                    *(uint32_t*)(O + idx) = pack_h2(v0, v1);
                } else if (EPI == 1) {
                    *(float2*)&Kout[idx] = make_float2(v0, v1);
                    const float2 y = *(const float2*)&Ybuf[idx];
                    *(uint32_t*)(O + idx) = pack_h2(fmaf(ad, v0, y.x), fmaf(ad, v1, y.y));
                } else {
                    const float2 y  = *(const float2*)&Ybuf[idx];
                    const float2 k1 = *(const float2*)&K1c[idx];
                    const float2 k2 = *(const float2*)&K2c[idx];
                    const float2 k3 = *(const float2*)&K3c[idx];
                    const float y0 = y.x + c6 * (k1.x + 2.0f*k2.x + 2.0f*k3.x + v0);
                    const float y1 = y.y + c6 * (k1.y + 2.0f*k2.y + 2.0f*k3.y + v1);
                    *(float2*)&Ybuf[idx] = make_float2(y0, y1);
                    *(float2*)&dout[((size_t)rows[h] * T_ + step + 1) * NFULL + cc] =
                        make_float2(y0, y1);
                    *(uint32_t*)(O + idx) = pack_h2(y0, y1);
                }
            }
        }
    }
}

// ---------------- persistent solver kernel ----------------
__global__ void __launch_bounds__(256, 1)
solver_k(const __half* __restrict__ W1t, const __half* __restrict__ W2t,
         const __half* __restrict__ W3t,
         const float* __restrict__ b1, const float* __restrict__ b2,
         const float* __restrict__ b3,
         float* __restrict__ dout, const float* __restrict__ tarr)
{
    extern __shared__ __align__(128) char sm[];
    const uint32_t smb = smem_u32(sm);

    __half* A  = g_A;
    __half* H1 = g_H1;
    __half* H2 = g_H2;
    float*  Kp[3] = { g_K1, g_K2, g_K3 };

    unsigned bar = 0;
    for (int s = 0; s < T_ - 1; s++) {
        const float dt = tarr[s + 1] - tarr[s];
        // evals 1..3: probe epilogue (EPI1)
        for (int e = 0; e < 3; e++) {
            const float alpha = (e < 2) ? 0.5f : 1.0f;
            if (bar) grid_barrier(bar);
            bar++;
            gemm_phase<128,128,32,64, D_,H_,0>(sm, smb, A, W1t, b1, H1,
                nullptr, nullptr, nullptr, nullptr, nullptr, nullptr, dt, s, 0.f);
            grid_barrier(bar); bar++;
            gemm_phase<128,128,32,64, H_,H_,0>(sm, smb, H1, W2t, b2, H2,
                nullptr, nullptr, nullptr, nullptr, nullptr, nullptr, dt, s, 0.f);
            grid_barrier(bar); bar++;
            gemm_phase<64,64,32,16, H_,D_,1>(sm, smb, H2, W3t, b3, A,
                Kp[e], nullptr, nullptr, nullptr, g_Y, nullptr, dt, s, alpha);
        }
        // eval 4: RK4 combine (EPI2)
        grid_barrier(bar); bar++;
        gemm_phase<128,128,32,64, D_,H_,0>(sm, smb, A, W1t, b1, H1,
            nullptr, nullptr, nullptr, nullptr, nullptr, nullptr, dt, s, 0.f);
        grid_barrier(bar); bar++;
        gemm_phase<128,128,32,64, H_,H_,0>(sm, smb, H1, W2t, b2, H2,
            nullptr, nullptr, nullptr, nullptr, nullptr, nullptr, dt, s, 0.f);
        grid_barrier(bar); bar++;
        gemm_phase<64,64,32,16, H_,D_,2>(sm, smb, H2, W3t, b3, A,
            nullptr, g_K1, g_K2, g_K3, g_Y, dout, dt, s, 0.f);
    }
}

// ---------------- weight prep: W[K,N] fp32 -> Wt[N,K] fp16 ----------------
__global__ void prep_w(const float* __restrict__ W,
                       __half* __restrict__ Wt, int K, int N)
{
    __shared__ float s[32][33];
    int k0 = blockIdx.y * 32, n0 = blockIdx.x * 32;
    int tx = threadIdx.x, ty = threadIdx.y;   // (32,8)
    #pragma unroll
    for (int r = 0; r < 4; r++)
        s[ty + r*8][tx] = W[(size_t)(k0 + ty + r*8) * N + n0 + tx];
    __syncthreads();
    #pragma unroll
    for (int r = 0; r < 4; r++) {
        int n = n0 + ty + r*8;
        Wt[(size_t)n * K + k0 + tx] = __float2half_rn(s[tx][ty + r*8]);
    }
}

__global__ void init_k(const float* __restrict__ fp, float* __restrict__ out) {
    int i = blockIdx.x * blockDim.x + threadIdx.x;
    if (i == 0) { g_bar_cnt = 0; g_bar_gen = 0; }
    if (i < M_ * D_) {
        float v = fp[i];
        g_Y[i] = v;
        g_A[i] = __float2half_rn(v);
        int m = i >> 8, d = i & 255;
        out[(size_t)m * T_ * D_ + d] = v;
    }
}

__global__ void tail_k(float* __restrict__ out, int out_size) {
    int i = PRED + blockIdx.x * blockDim.x + threadIdx.x;
    if (i < out_size) out[i] = 0.0f;
}

// ---------------- host ----------------
template<typename T> static T* sym(const void* s) {
    void* p = nullptr;
    cudaGetSymbolAddress(&p, s);
    return (T*)p;
}

extern "C" void kernel_launch(void* const* d_in, const int* in_sizes, int n_in,
                              void* d_out, int out_size)
{
    const float* fp   = (const float*)d_in[0];
    const float* tarr = (const float*)d_in[1];
    const float* W1   = (const float*)d_in[2];
    const float* b1   = (const float*)d_in[3];
    const float* W2   = (const float*)d_in[4];
    const float* b2   = (const float*)d_in[5];
    const float* W3   = (const float*)d_in[6];
    const float* b3   = (const float*)d_in[7];
    float* out = (float*)d_out;
    (void)in_sizes; (void)n_in;

    __half *W1t = sym<__half>(g_W1), *W2t = sym<__half>(g_W2), *W3t = sym<__half>(g_W3);

    constexpr int SM_BYTES = 3 * (128 + 128) * 128;   // 98304 (max over layer configs)
    cudaFuncSetAttribute((const void*)solver_k,
                         cudaFuncAttributeMaxDynamicSharedMemorySize, SM_BYTES);

    init_k<<<(M_*D_ + 255)/256, 256>>>(fp, out);
    if (out_size > PRED)
        tail_k<<<(out_size - PRED + 255)/256, 256>>>(out, out_size);
    prep_w<<<dim3(H_/32, D_/32), dim3(32,8)>>>(W1, W1t, D_, H_);
    prep_w<<<dim3(H_/32, H_/32), dim3(32,8)>>>(W2, W2t, H_, H_);
    prep_w<<<dim3(D_/32, H_/32), dim3(32,8)>>>(W3, W3t, H_, D_);

    solver_k<<<GRID_CTAS, 256, SM_BYTES>>>(W1t, W2t, W3t, b1, b2, b3, out, tarr);
}

// round 10
// speedup vs baseline: 1.1139x; 1.1139x over previous
#include <cuda_runtime.h>
#include <cuda_fp16.h>
#include <cstdint>
#include <cstddef>

#define S_ 4
#define B_ 512
#define D_ 256
#define H_ 1024
#define T_ 50
#define M_ (S_*B_)          // 2048
#define PRED (M_*T_*D_)

// ---------------- device scratch (no allocation allowed) ----------------
__device__ __half g_A [M_*D_];       // layer-1 input (probe state), fp16
__device__ __half g_H1[M_*H_];
__device__ __half g_H2[M_*H_];
__device__ float g_K1[M_*D_], g_K2[M_*D_], g_K3[M_*D_], g_Y[M_*D_];
// weights transposed to [N,K], single fp16
__device__ __half g_W1[H_*D_];
__device__ __half g_W2[H_*H_];
__device__ __half g_W3[D_*H_];

// ---------------- helpers ----------------
__device__ __forceinline__ uint32_t smem_u32(const void* p) {
    uint32_t a;
    asm("{ .reg .u64 t; cvta.to.shared.u64 t, %1; cvt.u32.u64 %0, t; }" : "=r"(a) : "l"(p));
    return a;
}
__device__ __forceinline__ void cp_async16(uint32_t saddr, const void* gaddr) {
    asm volatile("cp.async.cg.shared.global [%0], [%1], 16;" :: "r"(saddr), "l"(gaddr));
}
#define CP_COMMIT() asm volatile("cp.async.commit_group;" ::: "memory")
#define CP_WAIT1()  asm volatile("cp.async.wait_group 1;" ::: "memory")

__device__ __forceinline__ void ldsm_x4(uint32_t* r, uint32_t addr) {
    asm volatile("ldmatrix.sync.aligned.m8n8.x4.shared.b16 {%0,%1,%2,%3}, [%4];"
                 : "=r"(r[0]), "=r"(r[1]), "=r"(r[2]), "=r"(r[3]) : "r"(addr));
}
__device__ __forceinline__ void mma16816(float* c, const uint32_t* a, uint32_t b0, uint32_t b1) {
    asm volatile("mma.sync.aligned.m16n8k16.row.col.f32.f16.f16.f32 "
                 "{%0,%1,%2,%3}, {%4,%5,%6,%7}, {%8,%9}, {%0,%1,%2,%3};"
                 : "+f"(c[0]), "+f"(c[1]), "+f"(c[2]), "+f"(c[3])
                 : "r"(a[0]), "r"(a[1]), "r"(a[2]), "r"(a[3]), "r"(b0), "r"(b1));
}

__device__ __forceinline__ float fast_tanh(float x) {
    float t = __expf(2.0f * x);
    return 1.0f - 2.0f / (t + 1.0f);
}
__device__ __forceinline__ uint32_t pack_h2(float a, float b) {
    __half2 h = __floats2half2_rn(a, b);
    return *reinterpret_cast<uint32_t*>(&h);
}

// ---------------- tensor-core (HMMA fp16) GEMM ----------------
// C[M=2048, NFULL] = A[M,KDIM] @ W^T   (W stored [NFULL,KDIM] fp16)
// per-chunk stage = [A(BM rows) | W(BN rows)], 64 K-elems each.
// 3-stage cp.async pipeline, one __syncthreads + wait_group 1 per chunk.
// Inner loop: fragment double-buffering — ldmatrix for slice t+1 issued
// BEFORE the MMAs of slice t, hiding LDS latency under tensor work.
// EPI 0: tanh -> fp16 -> O
// EPI 1: k=C+bias; Kout=k; probe=Y+alpha*dt*k -> fp16 -> O
// EPI 2: k4=C+bias; y'=Y+dt/6*(K1+2K2+2K3+k4); Y=y'; traj store; fp16(y') -> O
template<int BM, int BN, int WM, int WN, int KDIM, int NFULL, int EPI>
__global__ void __launch_bounds__(256)
gemm_mma(const __half* __restrict__ A,
         const __half* __restrict__ W,
         const float* __restrict__ bias,
         __half* __restrict__ O,
         float* __restrict__ Kout,
         const float* __restrict__ K1c, const float* __restrict__ K2c, const float* __restrict__ K3c,
         float* __restrict__ Ybuf, float* __restrict__ dout,
         const float* __restrict__ tarr, int step, float alpha)
{
    constexpr int WARPS_M = BM / WM;
    constexpr int NC      = KDIM / 64;          // 64-elem K chunks
    constexpr int STAGE   = (BM + BN) * 128;
    constexpr int MI = WM / 16, NJ = WN / 8, NJJ = WN / 16;

    extern __shared__ __align__(128) char sm[];
    const uint32_t smb = smem_u32(sm);

    const int tid  = threadIdx.x;
    const int wid  = tid >> 5, lane = tid & 31;
    const int wm   = wid % WARPS_M, wn = wid / WARPS_M;
    const int bm   = blockIdx.y * BM;
    const int bn   = blockIdx.x * BN;

    float acc[MI][NJ][4];
    #pragma unroll
    for (int i = 0; i < MI; i++)
        #pragma unroll
        for (int j = 0; j < NJ; j++)
            #pragma unroll
            for (int q = 0; q < 4; q++) acc[i][j][q] = 0.0f;

    auto load_chunk = [&](int c, int slot) {
        const int k0 = c * 64;
        const uint32_t sb = smb + (uint32_t)slot * STAGE;
        #pragma unroll
        for (int i = tid; i < (BM + BN) * 8; i += 256) {
            const int seg = i & 7;
            const bool isA = i < BM * 8;
            const int row  = (isA ? i : i - BM * 8) >> 3;
            const __half* src = isA
                ? A + (size_t)(bm + row) * KDIM + k0 + seg * 8
                : W + (size_t)(bn + row) * KDIM + k0 + seg * 8;
            const uint32_t base = sb + (uint32_t)((isA ? row : BM + row)) * 128;
            cp_async16(base + (uint32_t)((seg ^ (row & 7)) << 4), src);
        }
    };

    // prologue: 2 stages in flight
    load_chunk(0, 0); CP_COMMIT();
    load_chunk(1, 1); CP_COMMIT();

    const int oct = lane >> 3, lr = lane & 7;

    // precomputed per-fragment row/ks bases
    const int arow0 = wm * WM + (oct & 1) * 8 + lr;   // + i*16
    const int aks0  = (oct >> 1);                     // + t*2
    const int brow0 = wn * WN + (oct >> 1) * 8 + lr;  // + jj*16
    const int bks0  = (oct & 1);                      // + t*2

    uint32_t af[2][MI][4], bf[2][NJJ][4];

    auto frag_load = [&](uint32_t Ab, uint32_t Bb, int t, int buf) {
        #pragma unroll
        for (int i = 0; i < MI; i++) {
            const int row = arow0 + i * 16;
            const int ks  = t * 2 + aks0;
            ldsm_x4(af[buf][i], Ab + (uint32_t)row * 128 + (uint32_t)((ks ^ (row & 7)) << 4));
        }
        #pragma unroll
        for (int jj = 0; jj < NJJ; jj++) {
            const int row = brow0 + jj * 16;
            const int ks  = t * 2 + bks0;
            ldsm_x4(bf[buf][jj], Bb + (uint32_t)row * 128 + (uint32_t)((ks ^ (row & 7)) << 4));
        }
    };

    for (int c = 0; c < NC; c++) {
        CP_WAIT1();            // chunk c complete (chunk c+1 may be in flight)
        __syncthreads();       // all warps done reading stage (c-1)%3
        if (c + 2 < NC) load_chunk(c + 2, (c + 2) % 3);
        CP_COMMIT();           // commit every iter (possibly empty) — uniform group algebra

        const uint32_t sb = smb + (uint32_t)(c % 3) * STAGE;
        const uint32_t Ab = sb;
        const uint32_t Bb = sb + BM * 128;

        frag_load(Ab, Bb, 0, 0);              // prime slice 0
        #pragma unroll
        for (int t = 0; t < 4; t++) {
            const int cur = t & 1, nxt = cur ^ 1;
            if (t < 3) frag_load(Ab, Bb, t + 1, nxt);   // LDSM ahead of MMAs
            #pragma unroll
            for (int i = 0; i < MI; i++)
                #pragma unroll
                for (int j = 0; j < NJ; j++)
                    mma16816(acc[i][j], af[cur][i],
                             bf[cur][j >> 1][(j & 1) * 2], bf[cur][j >> 1][(j & 1) * 2 + 1]);
        }
    }

    // ---------------- fused epilogue ----------------
    float dt = 0.0f;
    if (EPI != 0) dt = tarr[step + 1] - tarr[step];
    const float ad = alpha * dt;
    const float c6 = dt * (1.0f / 6.0f);

    const int r00   = bm + wm * WM + (lane >> 2);
    const int cbase = bn + wn * WN + (lane & 3) * 2;

    #pragma unroll
    for (int i = 0; i < MI; i++) {
        #pragma unroll
        for (int j = 0; j < NJ; j++) {
            const int cc = cbase + j * 8;
            const float2 bs = *(const float2*)&bias[cc];
            const int rows[2] = { r00 + i * 16, r00 + i * 16 + 8 };
            #pragma unroll
            for (int h = 0; h < 2; h++) {
                float v0 = acc[i][j][2*h + 0] + bs.x;
                float v1 = acc[i][j][2*h + 1] + bs.y;
                const size_t idx = (size_t)rows[h] * NFULL + cc;
                if (EPI == 0) {
                    v0 = fast_tanh(v0); v1 = fast_tanh(v1);
                    *(uint32_t*)(O + idx) = pack_h2(v0, v1);
                } else if (EPI == 1) {
                    *(float2*)&Kout[idx] = make_float2(v0, v1);
                    const float2 y = *(const float2*)&Ybuf[idx];
                    *(uint32_t*)(O + idx) = pack_h2(fmaf(ad, v0, y.x), fmaf(ad, v1, y.y));
                } else {
                    const float2 y  = *(const float2*)&Ybuf[idx];
                    const float2 k1 = *(const float2*)&K1c[idx];
                    const float2 k2 = *(const float2*)&K2c[idx];
                    const float2 k3 = *(const float2*)&K3c[idx];
                    const float y0 = y.x + c6 * (k1.x + 2.0f*k2.x + 2.0f*k3.x + v0);
                    const float y1 = y.y + c6 * (k1.y + 2.0f*k2.y + 2.0f*k3.y + v1);
                    *(float2*)&Ybuf[idx] = make_float2(y0, y1);
                    *(float2*)&dout[((size_t)rows[h] * T_ + step + 1) * NFULL + cc] =
                        make_float2(y0, y1);
                    *(uint32_t*)(O + idx) = pack_h2(y0, y1);
                }
            }
        }
    }
}

// ---------------- weight prep: W[K,N] fp32 -> Wt[N,K] fp16 ----------------
__global__ void prep_w(const float* __restrict__ W,
                       __half* __restrict__ Wt, int K, int N)
{
    __shared__ float s[32][33];
    int k0 = blockIdx.y * 32, n0 = blockIdx.x * 32;
    int tx = threadIdx.x, ty = threadIdx.y;   // (32,8)
    #pragma unroll
    for (int r = 0; r < 4; r++)
        s[ty + r*8][tx] = W[(size_t)(k0 + ty + r*8) * N + n0 + tx];
    __syncthreads();
    #pragma unroll
    for (int r = 0; r < 4; r++) {
        int n = n0 + ty + r*8;
        Wt[(size_t)n * K + k0 + tx] = __float2half_rn(s[tx][ty + r*8]);
    }
}

__global__ void init_k(const float* __restrict__ fp, float* __restrict__ out) {
    int i = blockIdx.x * blockDim.x + threadIdx.x;
    if (i < M_ * D_) {
        float v = fp[i];
        g_Y[i] = v;
        g_A[i] = __float2half_rn(v);
        int m = i >> 8, d = i & 255;
        out[(size_t)m * T_ * D_ + d] = v;
    }
}

__global__ void tail_k(float* __restrict__ out, int out_size) {
    int i = PRED + blockIdx.x * blockDim.x + threadIdx.x;
    if (i < out_size) out[i] = 0.0f;
}

// ---------------- host ----------------
template<typename T> static T* sym(const void* s) {
    void* p = nullptr;
    cudaGetSymbolAddress(&p, s);
    return (T*)p;
}

extern "C" void kernel_launch(void* const* d_in, const int* in_sizes, int n_in,
                              void* d_out, int out_size)
{
    const float* fp   = (const float*)d_in[0];
    const float* tarr = (const float*)d_in[1];
    const float* W1   = (const float*)d_in[2];
    const float* b1   = (const float*)d_in[3];
    const float* W2   = (const float*)d_in[4];
    const float* b2   = (const float*)d_in[5];
    const float* W3   = (const float*)d_in[6];
    const float* b3   = (const float*)d_in[7];
    float* out = (float*)d_out;
    (void)in_sizes; (void)n_in;

    __half *A  = sym<__half>(g_A);
    __half *H1 = sym<__half>(g_H1), *H2 = sym<__half>(g_H2);
    __half *W1t = sym<__half>(g_W1), *W2t = sym<__half>(g_W2), *W3t = sym<__half>(g_W3);
    float *K1 = sym<float>(g_K1), *K2 = sym<float>(g_K2), *K3 = sym<float>(g_K3);
    float *Y  = sym<float>(g_Y);

    // SMEM: 3 stages of (BM+BN)*128 bytes
    constexpr int SM_H = 3 * (128 + 128) * 128;  // 98304 (H layers)
    constexpr int SM_D = 3 * (64 + 64) * 128;    // 49152 (L3)
    cudaFuncSetAttribute((const void*)gemm_mma<128,128,32,64, D_,H_,0>,
                         cudaFuncAttributeMaxDynamicSharedMemorySize, SM_H);
    cudaFuncSetAttribute((const void*)gemm_mma<128,128,32,64, H_,H_,0>,
                         cudaFuncAttributeMaxDynamicSharedMemorySize, SM_H);
    cudaFuncSetAttribute((const void*)gemm_mma<64,64,32,16, H_,D_,1>,
                         cudaFuncAttributeMaxDynamicSharedMemorySize, SM_D);
    cudaFuncSetAttribute((const void*)gemm_mma<64,64,32,16, H_,D_,2>,
                         cudaFuncAttributeMaxDynamicSharedMemorySize, SM_D);

    init_k<<<(M_*D_ + 255)/256, 256>>>(fp, out);
    if (out_size > PRED)
        tail_k<<<(out_size - PRED + 255)/256, 256>>>(out, out_size);
    prep_w<<<dim3(H_/32, D_/32), dim3(32,8)>>>(W1, W1t, D_, H_);
    prep_w<<<dim3(H_/32, H_/32), dim3(32,8)>>>(W2, W2t, H_, H_);
    prep_w<<<dim3(D_/32, H_/32), dim3(32,8)>>>(W3, W3t, H_, D_);

    dim3 blk(256);
    dim3 gH(H_/128, M_/128);  // (8,16) = 128 CTAs
    dim3 gD(D_/64,  M_/64);   // (4,32) = 128 CTAs

    for (int s = 0; s < T_ - 1; s++) {
        // eval 1: f(Y)
        gemm_mma<128,128,32,64, D_,H_,0><<<gH, blk, SM_H>>>(A, W1t, b1, H1,
            nullptr, nullptr, nullptr, nullptr, nullptr, nullptr, tarr, s, 0.f);
        gemm_mma<128,128,32,64, H_,H_,0><<<gH, blk, SM_H>>>(H1, W2t, b2, H2,
            nullptr, nullptr, nullptr, nullptr, nullptr, nullptr, tarr, s, 0.f);
        gemm_mma<64,64,32,16, H_,D_,1><<<gD, blk, SM_D>>>(H2, W3t, b3, A,
            K1, nullptr, nullptr, nullptr, Y, nullptr, tarr, s, 0.5f);
        // eval 2
        gemm_mma<128,128,32,64, D_,H_,0><<<gH, blk, SM_H>>>(A, W1t, b1, H1,
            nullptr, nullptr, nullptr, nullptr, nullptr, nullptr, tarr, s, 0.f);
        gemm_mma<128,128,32,64, H_,H_,0><<<gH, blk, SM_H>>>(H1, W2t, b2, H2,
            nullptr, nullptr, nullptr, nullptr, nullptr, nullptr, tarr, s, 0.f);
        gemm_mma<64,64,32,16, H_,D_,1><<<gD, blk, SM_D>>>(H2, W3t, b3, A,
            K2, nullptr, nullptr, nullptr, Y, nullptr, tarr, s, 0.5f);
        // eval 3
        gemm_mma<128,128,32,64, D_,H_,0><<<gH, blk, SM_H>>>(A, W1t, b1, H1,
            nullptr, nullptr, nullptr, nullptr, nullptr, nullptr, tarr, s, 0.f);
        gemm_mma<128,128,32,64, H_,H_,0><<<gH, blk, SM_H>>>(H1, W2t, b2, H2,
            nullptr, nullptr, nullptr, nullptr, nullptr, nullptr, tarr, s, 0.f);
        gemm_mma<64,64,32,16, H_,D_,1><<<gD, blk, SM_D>>>(H2, W3t, b3, A,
            K3, nullptr, nullptr, nullptr, Y, nullptr, tarr, s, 1.0f);
        // eval 4 + RK4 combine fused
        gemm_mma<128,128,32,64, D_,H_,0><<<gH, blk, SM_H>>>(A, W1t, b1, H1,
            nullptr, nullptr, nullptr, nullptr, nullptr, nullptr, tarr, s, 0.f);
        gemm_mma<128,128,32,64, H_,H_,0><<<gH, blk, SM_H>>>(H1, W2t, b2, H2,
            nullptr, nullptr, nullptr, nullptr, nullptr, nullptr, tarr, s, 0.f);
        gemm_mma<64,64,32,16, H_,D_,2><<<gD, blk, SM_D>>>(H2, W3t, b3, A,
            nullptr, K1, K2, K3, Y, out, tarr, s, 0.f);
    }
}